// round 1
// baseline (speedup 1.0000x reference)
#include <cuda_runtime.h>
#include <cstdint>

// Problem shapes (fixed by dataset, but derived at runtime from in_sizes)
#define N_MAX 65536
#define K_MAX 4096
#define D_MAX 256

// Scratch (allocation-free rule: __device__ globals)
__device__ float g_c2[K_MAX];
__device__ float g_segsum[K_MAX * D_MAX];
__device__ int   g_segcnt[K_MAX];
__device__ int   g_labels[N_MAX];
__device__ float g_minq[N_MAX];   // min over k of (c2[k] - 2*x.c[k])
__device__ float g_loss;

// ---------------------------------------------------------------------------
// Zero the accumulators (graph replays re-run this every launch)
// ---------------------------------------------------------------------------
__global__ void init_kernel(int KD, int K) {
    int i = blockIdx.x * blockDim.x + threadIdx.x;
    if (i < KD) g_segsum[i] = 0.0f;
    if (i < K)  g_segcnt[i] = 0;
    if (i == 0) g_loss = 0.0f;
}

// ---------------------------------------------------------------------------
// c2[k] = sum_d centers[k][d]^2   (K blocks x 64 threads, D=256 via float4)
// ---------------------------------------------------------------------------
__global__ void c2_kernel(const float* __restrict__ C, int D) {
    int k = blockIdx.x;
    int t = threadIdx.x;
    float s = 0.0f;
    for (int d = t * 4; d < D; d += blockDim.x * 4) {
        float4 v = *(const float4*)(C + (size_t)k * D + d);
        s += v.x * v.x + v.y * v.y + v.z * v.z + v.w * v.w;
    }
    #pragma unroll
    for (int o = 16; o; o >>= 1) s += __shfl_down_sync(0xffffffffu, s, o);
    __shared__ float ws[2];
    if ((t & 31) == 0) ws[t >> 5] = s;
    __syncthreads();
    if (t == 0) g_c2[k] = ws[0] + ws[1];
}

// ---------------------------------------------------------------------------
// Assign kernel: fused SGEMM + argmin.
// Block = 256 threads (16x16), tile = 128 rows x 128 centers, D-chunk = 16.
// Each thread owns an 8x8 micro-tile; argmin kept in registers across all K.
// ---------------------------------------------------------------------------
#define BM 128
#define BK 128
#define DC 16
#define SPAD 4

__global__ __launch_bounds__(256) void assign_kernel(
    const float* __restrict__ X, const float* __restrict__ C,
    int N, int K, int D)
{
    __shared__ float As[DC][BM + SPAD];
    __shared__ float Bs[DC][BK + SPAD];

    int tid = threadIdx.x;
    int tx = tid & 15;          // center direction (8 cols each)
    int ty = tid >> 4;          // row direction (8 rows each)
    int rowBase = blockIdx.x * BM;

    float minv[8];
    int   mini[8];
    #pragma unroll
    for (int i = 0; i < 8; i++) { minv[i] = 3.0e38f; mini[i] = 0; }

    for (int k0 = 0; k0 < K; k0 += BK) {
        float acc[8][8];
        #pragma unroll
        for (int i = 0; i < 8; i++)
            #pragma unroll
            for (int j = 0; j < 8; j++) acc[i][j] = 0.0f;

        for (int d0 = 0; d0 < D; d0 += DC) {
            // Load A-tile (128x16) and B-tile (128x16), transposed into smem.
            #pragma unroll
            for (int p = 0; p < 2; p++) {
                int f4 = tid + p * 256;        // 0..511
                int m  = f4 >> 2;              // 0..127
                int q  = (f4 & 3) << 2;        // 0,4,8,12
                float4 va = *(const float4*)(X + (size_t)(rowBase + m) * D + d0 + q);
                float4 vb = *(const float4*)(C + (size_t)(k0 + m) * D + d0 + q);
                As[q + 0][m] = va.x; As[q + 1][m] = va.y;
                As[q + 2][m] = va.z; As[q + 3][m] = va.w;
                Bs[q + 0][m] = vb.x; Bs[q + 1][m] = vb.y;
                Bs[q + 2][m] = vb.z; Bs[q + 3][m] = vb.w;
            }
            __syncthreads();

            #pragma unroll
            for (int dc = 0; dc < DC; dc++) {
                float a[8], b[8];
                *(float4*)(a)     = *(const float4*)&As[dc][ty * 8];
                *(float4*)(a + 4) = *(const float4*)&As[dc][ty * 8 + 4];
                *(float4*)(b)     = *(const float4*)&Bs[dc][tx * 8];
                *(float4*)(b + 4) = *(const float4*)&Bs[dc][tx * 8 + 4];
                #pragma unroll
                for (int i = 0; i < 8; i++)
                    #pragma unroll
                    for (int j = 0; j < 8; j++)
                        acc[i][j] = fmaf(a[i], b[j], acc[i][j]);
            }
            __syncthreads();
        }

        // Fold this 128-center tile into the running argmin of (c2 - 2*dot).
        #pragma unroll
        for (int j = 0; j < 8; j++) {
            int col = k0 + tx * 8 + j;
            float c2 = __ldg(&g_c2[col]);
            #pragma unroll
            for (int i = 0; i < 8; i++) {
                float q = fmaf(-2.0f, acc[i][j], c2);
                if (q < minv[i]) { minv[i] = q; mini[i] = col; }
            }
        }
    }

    // Cross-thread argmin reduce over the 16 tx lanes sharing each row.
    // lane id = (ty&1)<<4 | tx, so xor over bits 0..3 stays within a warp.
    #pragma unroll
    for (int s = 1; s < 16; s <<= 1) {
        #pragma unroll
        for (int i = 0; i < 8; i++) {
            float ov = __shfl_xor_sync(0xffffffffu, minv[i], s);
            int   oi = __shfl_xor_sync(0xffffffffu, mini[i], s);
            if (ov < minv[i] || (ov == minv[i] && oi < mini[i])) {
                minv[i] = ov; mini[i] = oi;
            }
        }
    }

    if (tx == 0) {
        #pragma unroll
        for (int i = 0; i < 8; i++) {
            int row = rowBase + ty * 8 + i;
            g_labels[row] = mini[i];
            g_minq[row]   = minv[i];
        }
    }
}

// ---------------------------------------------------------------------------
// Scatter: seg_sum += x, seg_cnt += 1, loss += x2 + minq, labels -> out.
// 4 rows per 256-thread block; 64 threads (float4) per row.
// ---------------------------------------------------------------------------
__global__ __launch_bounds__(256) void scatter_kernel(
    const float* __restrict__ X, float* __restrict__ out_labels, int D)
{
    int r    = blockIdx.x * 4 + (threadIdx.x >> 6);
    int lane = threadIdx.x & 63;
    int lab  = g_labels[r];

    float4 v = *(const float4*)(X + (size_t)r * D + lane * 4);
    float* dst = g_segsum + (size_t)lab * D + lane * 4;
    atomicAdd(dst + 0, v.x);
    atomicAdd(dst + 1, v.y);
    atomicAdd(dst + 2, v.z);
    atomicAdd(dst + 3, v.w);

    float part = v.x * v.x + v.y * v.y + v.z * v.z + v.w * v.w;
    if (lane == 0) {
        part += g_minq[r];                 // x2 + (c2 - 2 x.c) = d2_min
        atomicAdd(&g_segcnt[lab], 1);
        out_labels[r] = (float)lab;
    }

    // Block-reduce 'part', one global atomic per block (avoid single-addr REDG wall)
    #pragma unroll
    for (int o = 16; o; o >>= 1) part += __shfl_down_sync(0xffffffffu, part, o);
    __shared__ float ws[8];
    if ((threadIdx.x & 31) == 0) ws[threadIdx.x >> 5] = part;
    __syncthreads();
    if (threadIdx.x < 8) {
        float s = ws[threadIdx.x];
        #pragma unroll
        for (int o = 4; o; o >>= 1) s += __shfl_down_sync(0xffu, s, o);
        if (threadIdx.x == 0) atomicAdd(&g_loss, s);
    }
}

// ---------------------------------------------------------------------------
// Finalize: new_centers, new_counts, loss
// ---------------------------------------------------------------------------
__global__ void finalize_kernel(
    const float* __restrict__ centers, const int* __restrict__ counts,
    float* __restrict__ out_centers, float* __restrict__ out_counts,
    float* __restrict__ out_loss, int K, int D, float invN)
{
    int idx = blockIdx.x * blockDim.x + threadIdx.x;
    if (idx < K * D) {
        int k = idx / D;
        float c0  = (float)counts[k];
        float cnt = (float)g_segcnt[k];
        out_centers[idx] = (c0 * centers[idx] + g_segsum[idx]) / (c0 + cnt);
    }
    if (idx < K) out_counts[idx] = (float)(counts[idx] + g_segcnt[idx]);
    if (idx == 0) out_loss[0] = g_loss * invN;
}

// ---------------------------------------------------------------------------
extern "C" void kernel_launch(void* const* d_in, const int* in_sizes, int n_in,
                              void* d_out, int out_size)
{
    const float* X      = (const float*)d_in[0];   // embedded [N,D]
    const float* C      = (const float*)d_in[1];   // centers  [K,D]
    const int*   counts = (const int*)  d_in[2];   // counts   [K]

    int K = in_sizes[2];
    int D = in_sizes[1] / K;
    int N = in_sizes[0] / D;
    int KD = K * D;

    float* out         = (float*)d_out;
    float* out_labels  = out;                       // [N]
    float* out_centers = out + N;                   // [K*D]
    float* out_counts  = out + N + (size_t)KD;      // [K]
    float* out_loss    = out_counts + K;            // [1]

    init_kernel<<<(KD + 255) / 256, 256>>>(KD, K);
    c2_kernel<<<K, 64>>>(C, D);
    assign_kernel<<<N / BM, 256>>>(X, C, N, K, D);
    scatter_kernel<<<N / 4, 256>>>(X, out_labels, D);
    finalize_kernel<<<(KD + 255) / 256, 256>>>(C, counts, out_centers, out_counts,
                                               out_loss, K, D, 1.0f / (float)N);
}